// round 16
// baseline (speedup 1.0000x reference)
#include <cuda_runtime.h>
#include <cuda_fp16.h>
#include <cstdint>
#include <cstring>

// Conv2d 3x3 s1 p1: x[256,224,224] f32, w[256,256,3,3] f32 -> out[256,224,224] f32
// Winograd F(2x2,3x3) on fp16 tensor cores (mma.sync m16n8k16, f32 acc).
// Round 16: periphery harvest — wino_w folded into wino_in launch; wino_out
// widened to 4 tiles/thread (8B M loads, full sectors). GEMM = round-15
// persistent config, untouched.

#define H 224
#define W 224
#define C 256
#define NTILE 12544          // 112*112 output tiles of 2x2
#define TW 112               // tiles per image row

#define NCTA 304             // 2 per SM x 152 SMs (GB300)
#define NITEM 3584           // 112 tb x 16 k x 2 coh

// U: [k(16)][ci(256)][tile(12544)] fp16
__device__ __align__(16) __half g_U[16ull * C * NTILE];
// M: [k(16)][co(256)][tile(12544)] fp16
__device__ __align__(16) __half g_M[16ull * C * NTILE];
// W': [k(16)][coh(2)][kc(8)][co(128)][j(32)] fp16, ci = kc*32+j
__device__ __align__(16) __half g_Wt[16ull * 2 * 8 * 128 * 32];

// ---------------- fused prep: input transform + weight transform ------------
// blocks x<49: U = B^T d B (2 tiles/thread); block x==49: W' = G w G^T for ci
__global__ void wino_prep_kernel(const float* __restrict__ x,
                                 const float* __restrict__ w) {
    const int ci = blockIdx.y;
    const int tid = threadIdx.x;

    if (blockIdx.x == 49) {
        // weight transform: 128 threads x 2 co for this ci
#pragma unroll
        for (int h = 0; h < 2; ++h) {
            int co = tid + h * 128;
            float g[3][3];
#pragma unroll
            for (int r = 0; r < 3; ++r)
#pragma unroll
                for (int c = 0; c < 3; ++c)
                    g[r][c] = w[((co * C + ci) * 3 + r) * 3 + c];
            float t[4][3];
#pragma unroll
            for (int c = 0; c < 3; ++c) {
                t[0][c] = g[0][c];
                t[1][c] = 0.5f * (g[0][c] + g[1][c] + g[2][c]);
                t[2][c] = 0.5f * (g[0][c] - g[1][c] + g[2][c]);
                t[3][c] = g[2][c];
            }
            float u[4][4];
#pragma unroll
            for (int r = 0; r < 4; ++r) {
                u[r][0] = t[r][0];
                u[r][1] = 0.5f * (t[r][0] + t[r][1] + t[r][2]);
                u[r][2] = 0.5f * (t[r][0] - t[r][1] + t[r][2]);
                u[r][3] = t[r][2];
            }
            int coh = co >> 7, col = co & 127, kc = ci >> 5, j = ci & 31;
#pragma unroll
            for (int k = 0; k < 16; ++k)
                g_Wt[((((size_t)(k * 2 + coh) * 8 + kc) * 128 + col) << 5) + j] =
                    __float2half_rn(u[k >> 2][k & 3]);
        }
        return;
    }

    // input transform, 2 tiles per thread
    int p = blockIdx.x * 128 + tid;    // 0..6271 tile-pairs
    int ty = p / 56, px = p - ty * 56;
    int tx0 = px * 2;
    int y0 = 2 * ty - 1, x0 = 2 * tx0 - 1;
    const float* xp = x + (size_t)ci * H * W;
    float d[4][6];
#pragma unroll
    for (int r = 0; r < 4; ++r) {
        int yy = y0 + r;
        bool yok = (unsigned)yy < 224u;
        const float* row = xp + yy * W;
#pragma unroll
        for (int c = 0; c < 6; ++c) {
            int xx = x0 + c;
            d[r][c] = (yok && (unsigned)xx < 224u) ? row[xx] : 0.0f;
        }
    }
    float tr[4][6];
#pragma unroll
    for (int c = 0; c < 6; ++c) {
        tr[0][c] = d[0][c] - d[2][c];
        tr[1][c] = d[1][c] + d[2][c];
        tr[2][c] = d[2][c] - d[1][c];
        tr[3][c] = d[1][c] - d[3][c];
    }
    size_t t0 = (size_t)ty * TW + tx0;
#pragma unroll
    for (int r = 0; r < 4; ++r) {
        float ua[4], ub[4];
        ua[0] = tr[r][0] - tr[r][2];
        ua[1] = tr[r][1] + tr[r][2];
        ua[2] = tr[r][2] - tr[r][1];
        ua[3] = tr[r][1] - tr[r][3];
        ub[0] = tr[r][2] - tr[r][4];
        ub[1] = tr[r][3] + tr[r][4];
        ub[2] = tr[r][4] - tr[r][3];
        ub[3] = tr[r][3] - tr[r][5];
#pragma unroll
        for (int c = 0; c < 4; ++c) {
            int k = r * 4 + c;
            *(__half2*)&g_U[(size_t)(k * C + ci) * NTILE + t0] =
                __floats2half2_rn(ua[c], ub[c]);
        }
    }
}

// ---------------- persistent batched component GEMMs (round-15, frozen) -----
__device__ __forceinline__ uint32_t smem_u32(const void* p) {
    uint32_t a;
    asm("{ .reg .u64 t; cvta.to.shared.u64 t, %1; cvt.u32.u64 %0, t; }" : "=r"(a) : "l"(p));
    return a;
}
__device__ __forceinline__ void cp16(uint32_t dst, const void* src) {
    asm volatile("cp.async.cg.shared.global [%0], [%1], 16;" :: "r"(dst), "l"(src) : "memory");
}
__device__ __forceinline__ void cp_commit() {
    asm volatile("cp.async.commit_group;" ::: "memory");
}
__device__ __forceinline__ void ldsm_x4(uint32_t* r, uint32_t a) {
    asm volatile("ldmatrix.sync.aligned.m8n8.x4.shared.b16 {%0,%1,%2,%3}, [%4];"
                 : "=r"(r[0]), "=r"(r[1]), "=r"(r[2]), "=r"(r[3]) : "r"(a));
}
__device__ __forceinline__ void ldsm_x2t(uint32_t* r, uint32_t a) {
    asm volatile("ldmatrix.sync.aligned.m8n8.x2.trans.shared.b16 {%0,%1}, [%2];"
                 : "=r"(r[0]), "=r"(r[1]) : "r"(a));
}
__device__ __forceinline__ void mma16816(float* d, const uint32_t* a, const uint32_t* b) {
    asm volatile(
        "mma.sync.aligned.m16n8k16.row.col.f32.f16.f16.f32 "
        "{%0,%1,%2,%3}, {%4,%5,%6,%7}, {%8,%9}, {%0,%1,%2,%3};"
        : "+f"(d[0]), "+f"(d[1]), "+f"(d[2]), "+f"(d[3])
        : "r"(a[0]), "r"(a[1]), "r"(a[2]), "r"(a[3]), "r"(b[0]), "r"(b[1]));
}

#define A_BYTES 10240                     // 128 rows * 80B (64 used)
#define B_BYTES 7680                      // 32 rows * 240B (224 used)
#define STAGE_BYTES (A_BYTES + B_BYTES)   // 17920
#define NBUF 4
#define SMEM_SZ (NBUF * STAGE_BYTES)      // 71680

__device__ __forceinline__ void load_stage(int j, uint32_t sbase, int tid, int cta) {
    int e = cta + (j >> 3) * NCTA;
    if (e >= NITEM) return;
    int kc  = j & 7;
    int tb  = e >> 5;
    int r   = e & 31;
    int k   = r >> 1;
    int coh = r & 1;
    const __half* wsrc = g_Wt + (((size_t)(k * 2 + coh) * 8 + kc) << 12);
#pragma unroll
    for (int v = tid; v < 512; v += 256) {
        cp16(sbase + (v >> 2) * 80 + (v & 3) * 16, (const char*)wsrc + v * 16);
    }
    uint32_t bbase = sbase + A_BYTES;
    const __half* usrc = g_U + (size_t)(k * C + kc * 32) * NTILE + tb * 112;
    for (int v = tid; v < 448; v += 256) {
        int row = v / 14;
        int cv  = v - row * 14;
        cp16(bbase + row * 240 + cv * 16,
             (const char*)(usrc + (size_t)row * NTILE) + cv * 16);
    }
}

__device__ __forceinline__ void epilogue_k(float acc[2][7][4], int lane,
                                           int wm, int wn, int k, int coh, int tb) {
    const int rq = lane >> 2;
    const int cq = (lane & 3) * 2;
#pragma unroll
    for (int m = 0; m < 2; ++m)
#pragma unroll
        for (int n = 0; n < 7; ++n) {
            int co  = coh * 128 + wm * 32 + m * 16 + rq;
            int col = wn * 56 + n * 8 + cq;
            size_t base = (size_t)(k * C + co) * NTILE + tb * 112 + col;
            *(__half2*)&g_M[base] =
                __floats2half2_rn(acc[m][n][0], acc[m][n][1]);
            *(__half2*)&g_M[base + 8ull * NTILE] =
                __floats2half2_rn(acc[m][n][2], acc[m][n][3]);
        }
}

__global__ __launch_bounds__(256, 2) void wino_gemm_kernel() {
    extern __shared__ __align__(16) unsigned char smbuf[];
    const uint32_t sb = smem_u32(smbuf);
    const int tid  = threadIdx.x;
    const int lane = tid & 31;
    const int wid  = tid >> 5;
    const int wm   = wid & 3;
    const int wn   = wid >> 2;
    const int cta  = blockIdx.x;

    const int nitems = (NITEM - 1 - cta) / NCTA + 1;
    const int NS = nitems * 8;

    float acc[2][7][4];
#pragma unroll
    for (int m = 0; m < 2; ++m)
#pragma unroll
        for (int n = 0; n < 7; ++n)
#pragma unroll
            for (int q = 0; q < 4; ++q) acc[m][n][q] = 0.0f;

    uint32_t aA0[2], aB0[7];
#pragma unroll
    for (int m = 0; m < 2; ++m)
        aA0[m] = sb + (wm * 32 + m * 16 + (lane & 15)) * 80 + (lane >> 4) * 16;
#pragma unroll
    for (int n = 0; n < 7; ++n)
        aB0[n] = sb + A_BYTES + (lane & 15) * 240 + wn * 112 + n * 16;

    load_stage(0, sb, tid, cta);
    cp_commit();
    load_stage(1, sb + STAGE_BYTES, tid, cta);
    cp_commit();
    load_stage(2, sb + 2 * STAGE_BYTES, tid, cta);
    cp_commit();

    for (int i = 0; i < NS; ++i) {
        asm volatile("cp.async.wait_group 2;" ::: "memory");
        __syncthreads();
        if (i + 3 < NS)
            load_stage(i + 3, sb + ((i + 3) & 3) * STAGE_BYTES, tid, cta);
        cp_commit();

        const uint32_t off = (i & 3) * STAGE_BYTES;
#pragma unroll
        for (int ks = 0; ks < 2; ++ks) {
            uint32_t a[2][4], b[7][2];
#pragma unroll
            for (int m = 0; m < 2; ++m) ldsm_x4(a[m], aA0[m] + off + ks * 32);
#pragma unroll
            for (int n = 0; n < 7; ++n) ldsm_x2t(b[n], aB0[n] + off + ks * 16 * 240);
#pragma unroll
            for (int m = 0; m < 2; ++m)
#pragma unroll
                for (int n = 0; n < 7; ++n) mma16816(acc[m][n], a[m], b[n]);
        }

        if ((i & 7) == 7) {
            int e   = cta + (i >> 3) * NCTA;
            int tb  = e >> 5;
            int r   = e & 31;
            epilogue_k(acc, lane, wm, wn, r >> 1, r & 1, tb);
#pragma unroll
            for (int m = 0; m < 2; ++m)
#pragma unroll
                for (int n = 0; n < 7; ++n)
#pragma unroll
                    for (int q = 0; q < 4; ++q) acc[m][n][q] = 0.0f;
        }
    }
}

// ------- inverse transform: y = A^T M A, 4 tiles per thread (8B loads) ------
__global__ void wino_out_kernel(float* __restrict__ out) {
    int p = blockIdx.x * 128 + threadIdx.x;    // tile-quads, 3136 per co
    if (p >= 3136) return;
    int co = blockIdx.y;
    int ty = p / 28, qx = p - ty * 28;         // 28 quads per tile row
    size_t t0 = (size_t)ty * TW + qx * 4;

    float m[4][4][4];   // [tile][r][c]
#pragma unroll
    for (int k = 0; k < 16; ++k) {
        uint2 v = *(const uint2*)&g_M[(size_t)(k * C + co) * NTILE + t0];
        __half2 h01, h23;
        memcpy(&h01, &v.x, 4);
        memcpy(&h23, &v.y, 4);
        float2 f01 = __half22float2(h01);
        float2 f23 = __half22float2(h23);
        int r = k >> 2, c = k & 3;
        m[0][r][c] = f01.x;
        m[1][r][c] = f01.y;
        m[2][r][c] = f23.x;
        m[3][r][c] = f23.y;
    }

    float row0[8], row1[8];
#pragma unroll
    for (int q = 0; q < 4; ++q) {
        float r0[4], r1[4];
#pragma unroll
        for (int c = 0; c < 4; ++c) {
            r0[c] = m[q][0][c] + m[q][1][c] + m[q][2][c];
            r1[c] = m[q][1][c] - m[q][2][c] - m[q][3][c];
        }
        row0[2 * q]     = r0[0] + r0[1] + r0[2];
        row0[2 * q + 1] = r0[1] - r0[2] - r0[3];
        row1[2 * q]     = r1[0] + r1[1] + r1[2];
        row1[2 * q + 1] = r1[1] - r1[2] - r1[3];
    }

    float* pp = out + ((size_t)co * H + 2 * ty) * W + 8 * qx;
    *(float4*)pp       = make_float4(row0[0], row0[1], row0[2], row0[3]);
    *(float4*)(pp + 4) = make_float4(row0[4], row0[5], row0[6], row0[7]);
    *(float4*)(pp + W)     = make_float4(row1[0], row1[1], row1[2], row1[3]);
    *(float4*)(pp + W + 4) = make_float4(row1[4], row1[5], row1[6], row1[7]);
}

extern "C" void kernel_launch(void* const* d_in, const int* in_sizes, int n_in,
                              void* d_out, int out_size) {
    const float* x = (const float*)d_in[0];   // [1,256,224,224]
    const float* w = (const float*)d_in[1];   // [256,256,3,3]
    float* out = (float*)d_out;               // [256,224,224]
    (void)in_sizes; (void)n_in; (void)out_size;

    wino_prep_kernel<<<dim3(50, C), 128>>>(x, w);

    static int smem_set = 0;
    if (!smem_set) {
        cudaFuncSetAttribute(wino_gemm_kernel,
                             cudaFuncAttributeMaxDynamicSharedMemorySize, SMEM_SZ);
        smem_set = 1;
    }
    wino_gemm_kernel<<<NCTA, 256, SMEM_SZ>>>();
    wino_out_kernel<<<dim3(25, C), 128>>>(out);
}

// round 17
// speedup vs baseline: 1.0493x; 1.0493x over previous
#include <cuda_runtime.h>
#include <cuda_fp16.h>
#include <cstdint>
#include <cstring>

// Conv2d 3x3 s1 p1: x[256,224,224] f32, w[256,256,3,3] f32 -> out[256,224,224] f32
// Winograd F(2x2,3x3) on fp16 tensor cores (mma.sync m16n8k16, f32 acc).
// Round 17: round-15 config (separate wino_w / wino_in, persistent GEMM) with
// ONE change: wino_out widened to 4 tiles/thread (8B M loads, full sectors).

#define H 224
#define W 224
#define C 256
#define NTILE 12544          // 112*112 output tiles of 2x2
#define TW 112               // tiles per image row

#define NCTA 304             // 2 per SM x 152 SMs (GB300)
#define NITEM 3584           // 112 tb x 16 k x 2 coh

// U: [k(16)][ci(256)][tile(12544)] fp16
__device__ __align__(16) __half g_U[16ull * C * NTILE];
// M: [k(16)][co(256)][tile(12544)] fp16
__device__ __align__(16) __half g_M[16ull * C * NTILE];
// W': [k(16)][coh(2)][kc(8)][co(128)][j(32)] fp16, ci = kc*32+j
__device__ __align__(16) __half g_Wt[16ull * 2 * 8 * 128 * 32];

// ---------------- weight transform: W' = G w G^T ----------------
__global__ void wino_w_kernel(const float* __restrict__ w) {
    int i = blockIdx.x * blockDim.x + threadIdx.x;   // 65536 = co*ci
    if (i >= C * C) return;
    int ci = i & 255;
    int co = i >> 8;
    float g[3][3];
#pragma unroll
    for (int r = 0; r < 3; ++r)
#pragma unroll
        for (int c = 0; c < 3; ++c)
            g[r][c] = w[((co * C + ci) * 3 + r) * 3 + c];
    float t[4][3];
#pragma unroll
    for (int c = 0; c < 3; ++c) {
        t[0][c] = g[0][c];
        t[1][c] = 0.5f * (g[0][c] + g[1][c] + g[2][c]);
        t[2][c] = 0.5f * (g[0][c] - g[1][c] + g[2][c]);
        t[3][c] = g[2][c];
    }
    float u[4][4];
#pragma unroll
    for (int r = 0; r < 4; ++r) {
        u[r][0] = t[r][0];
        u[r][1] = 0.5f * (t[r][0] + t[r][1] + t[r][2]);
        u[r][2] = 0.5f * (t[r][0] - t[r][1] + t[r][2]);
        u[r][3] = t[r][2];
    }
    int coh = co >> 7, col = co & 127, kc = ci >> 5, j = ci & 31;
#pragma unroll
    for (int k = 0; k < 16; ++k)
        g_Wt[((((size_t)(k * 2 + coh) * 8 + kc) * 128 + col) << 5) + j] =
            __float2half_rn(u[k >> 2][k & 3]);
}

// ---------------- input transform: U = B^T d B, 2 tiles per thread ----------
__global__ void wino_in_kernel(const float* __restrict__ x) {
    int p = blockIdx.x * 128 + threadIdx.x;    // 0..6271 tile-pairs, grid.x = 49
    int ci = blockIdx.y;
    int ty = p / 56, px = p - ty * 56;
    int tx0 = px * 2;
    int y0 = 2 * ty - 1, x0 = 2 * tx0 - 1;
    const float* xp = x + (size_t)ci * H * W;
    float d[4][6];
#pragma unroll
    for (int r = 0; r < 4; ++r) {
        int yy = y0 + r;
        bool yok = (unsigned)yy < 224u;
        const float* row = xp + yy * W;
#pragma unroll
        for (int c = 0; c < 6; ++c) {
            int xx = x0 + c;
            d[r][c] = (yok && (unsigned)xx < 224u) ? row[xx] : 0.0f;
        }
    }
    float tr[4][6];
#pragma unroll
    for (int c = 0; c < 6; ++c) {
        tr[0][c] = d[0][c] - d[2][c];
        tr[1][c] = d[1][c] + d[2][c];
        tr[2][c] = d[2][c] - d[1][c];
        tr[3][c] = d[1][c] - d[3][c];
    }
    size_t t0 = (size_t)ty * TW + tx0;
#pragma unroll
    for (int r = 0; r < 4; ++r) {
        float ua[4], ub[4];
        ua[0] = tr[r][0] - tr[r][2];
        ua[1] = tr[r][1] + tr[r][2];
        ua[2] = tr[r][2] - tr[r][1];
        ua[3] = tr[r][1] - tr[r][3];
        ub[0] = tr[r][2] - tr[r][4];
        ub[1] = tr[r][3] + tr[r][4];
        ub[2] = tr[r][4] - tr[r][3];
        ub[3] = tr[r][3] - tr[r][5];
#pragma unroll
        for (int c = 0; c < 4; ++c) {
            int k = r * 4 + c;
            *(__half2*)&g_U[(size_t)(k * C + ci) * NTILE + t0] =
                __floats2half2_rn(ua[c], ub[c]);
        }
    }
}

// ---------------- persistent batched component GEMMs (frozen) ----------------
__device__ __forceinline__ uint32_t smem_u32(const void* p) {
    uint32_t a;
    asm("{ .reg .u64 t; cvta.to.shared.u64 t, %1; cvt.u32.u64 %0, t; }" : "=r"(a) : "l"(p));
    return a;
}
__device__ __forceinline__ void cp16(uint32_t dst, const void* src) {
    asm volatile("cp.async.cg.shared.global [%0], [%1], 16;" :: "r"(dst), "l"(src) : "memory");
}
__device__ __forceinline__ void cp_commit() {
    asm volatile("cp.async.commit_group;" ::: "memory");
}
__device__ __forceinline__ void ldsm_x4(uint32_t* r, uint32_t a) {
    asm volatile("ldmatrix.sync.aligned.m8n8.x4.shared.b16 {%0,%1,%2,%3}, [%4];"
                 : "=r"(r[0]), "=r"(r[1]), "=r"(r[2]), "=r"(r[3]) : "r"(a));
}
__device__ __forceinline__ void ldsm_x2t(uint32_t* r, uint32_t a) {
    asm volatile("ldmatrix.sync.aligned.m8n8.x2.trans.shared.b16 {%0,%1}, [%2];"
                 : "=r"(r[0]), "=r"(r[1]) : "r"(a));
}
__device__ __forceinline__ void mma16816(float* d, const uint32_t* a, const uint32_t* b) {
    asm volatile(
        "mma.sync.aligned.m16n8k16.row.col.f32.f16.f16.f32 "
        "{%0,%1,%2,%3}, {%4,%5,%6,%7}, {%8,%9}, {%0,%1,%2,%3};"
        : "+f"(d[0]), "+f"(d[1]), "+f"(d[2]), "+f"(d[3])
        : "r"(a[0]), "r"(a[1]), "r"(a[2]), "r"(a[3]), "r"(b[0]), "r"(b[1]));
}

#define A_BYTES 10240                     // 128 rows * 80B (64 used)
#define B_BYTES 7680                      // 32 rows * 240B (224 used)
#define STAGE_BYTES (A_BYTES + B_BYTES)   // 17920
#define NBUF 4
#define SMEM_SZ (NBUF * STAGE_BYTES)      // 71680

__device__ __forceinline__ void load_stage(int j, uint32_t sbase, int tid, int cta) {
    int e = cta + (j >> 3) * NCTA;
    if (e >= NITEM) return;
    int kc  = j & 7;
    int tb  = e >> 5;
    int r   = e & 31;
    int k   = r >> 1;
    int coh = r & 1;
    const __half* wsrc = g_Wt + (((size_t)(k * 2 + coh) * 8 + kc) << 12);
#pragma unroll
    for (int v = tid; v < 512; v += 256) {
        cp16(sbase + (v >> 2) * 80 + (v & 3) * 16, (const char*)wsrc + v * 16);
    }
    uint32_t bbase = sbase + A_BYTES;
    const __half* usrc = g_U + (size_t)(k * C + kc * 32) * NTILE + tb * 112;
    for (int v = tid; v < 448; v += 256) {
        int row = v / 14;
        int cv  = v - row * 14;
        cp16(bbase + row * 240 + cv * 16,
             (const char*)(usrc + (size_t)row * NTILE) + cv * 16);
    }
}

__device__ __forceinline__ void epilogue_k(float acc[2][7][4], int lane,
                                           int wm, int wn, int k, int coh, int tb) {
    const int rq = lane >> 2;
    const int cq = (lane & 3) * 2;
#pragma unroll
    for (int m = 0; m < 2; ++m)
#pragma unroll
        for (int n = 0; n < 7; ++n) {
            int co  = coh * 128 + wm * 32 + m * 16 + rq;
            int col = wn * 56 + n * 8 + cq;
            size_t base = (size_t)(k * C + co) * NTILE + tb * 112 + col;
            *(__half2*)&g_M[base] =
                __floats2half2_rn(acc[m][n][0], acc[m][n][1]);
            *(__half2*)&g_M[base + 8ull * NTILE] =
                __floats2half2_rn(acc[m][n][2], acc[m][n][3]);
        }
}

__global__ __launch_bounds__(256, 2) void wino_gemm_kernel() {
    extern __shared__ __align__(16) unsigned char smbuf[];
    const uint32_t sb = smem_u32(smbuf);
    const int tid  = threadIdx.x;
    const int lane = tid & 31;
    const int wid  = tid >> 5;
    const int wm   = wid & 3;
    const int wn   = wid >> 2;
    const int cta  = blockIdx.x;

    const int nitems = (NITEM - 1 - cta) / NCTA + 1;
    const int NS = nitems * 8;

    float acc[2][7][4];
#pragma unroll
    for (int m = 0; m < 2; ++m)
#pragma unroll
        for (int n = 0; n < 7; ++n)
#pragma unroll
            for (int q = 0; q < 4; ++q) acc[m][n][q] = 0.0f;

    uint32_t aA0[2], aB0[7];
#pragma unroll
    for (int m = 0; m < 2; ++m)
        aA0[m] = sb + (wm * 32 + m * 16 + (lane & 15)) * 80 + (lane >> 4) * 16;
#pragma unroll
    for (int n = 0; n < 7; ++n)
        aB0[n] = sb + A_BYTES + (lane & 15) * 240 + wn * 112 + n * 16;

    load_stage(0, sb, tid, cta);
    cp_commit();
    load_stage(1, sb + STAGE_BYTES, tid, cta);
    cp_commit();
    load_stage(2, sb + 2 * STAGE_BYTES, tid, cta);
    cp_commit();

    for (int i = 0; i < NS; ++i) {
        asm volatile("cp.async.wait_group 2;" ::: "memory");
        __syncthreads();
        if (i + 3 < NS)
            load_stage(i + 3, sb + ((i + 3) & 3) * STAGE_BYTES, tid, cta);
        cp_commit();

        const uint32_t off = (i & 3) * STAGE_BYTES;
#pragma unroll
        for (int ks = 0; ks < 2; ++ks) {
            uint32_t a[2][4], b[7][2];
#pragma unroll
            for (int m = 0; m < 2; ++m) ldsm_x4(a[m], aA0[m] + off + ks * 32);
#pragma unroll
            for (int n = 0; n < 7; ++n) ldsm_x2t(b[n], aB0[n] + off + ks * 16 * 240);
#pragma unroll
            for (int m = 0; m < 2; ++m)
#pragma unroll
                for (int n = 0; n < 7; ++n) mma16816(acc[m][n], a[m], b[n]);
        }

        if ((i & 7) == 7) {
            int e   = cta + (i >> 3) * NCTA;
            int tb  = e >> 5;
            int r   = e & 31;
            epilogue_k(acc, lane, wm, wn, r >> 1, r & 1, tb);
#pragma unroll
            for (int m = 0; m < 2; ++m)
#pragma unroll
                for (int n = 0; n < 7; ++n)
#pragma unroll
                    for (int q = 0; q < 4; ++q) acc[m][n][q] = 0.0f;
        }
    }
}

// ------- inverse transform: y = A^T M A, 4 tiles per thread (8B loads) ------
__global__ void wino_out_kernel(float* __restrict__ out) {
    int p = blockIdx.x * 128 + threadIdx.x;    // tile-quads, 3136 per co
    if (p >= 3136) return;
    int co = blockIdx.y;
    int ty = p / 28, qx = p - ty * 28;         // 28 quads per tile row
    size_t t0 = (size_t)ty * TW + qx * 4;

    float m[4][4][4];   // [tile][r][c]
#pragma unroll
    for (int k = 0; k < 16; ++k) {
        uint2 v = *(const uint2*)&g_M[(size_t)(k * C + co) * NTILE + t0];
        __half2 h01, h23;
        memcpy(&h01, &v.x, 4);
        memcpy(&h23, &v.y, 4);
        float2 f01 = __half22float2(h01);
        float2 f23 = __half22float2(h23);
        int r = k >> 2, c = k & 3;
        m[0][r][c] = f01.x;
        m[1][r][c] = f01.y;
        m[2][r][c] = f23.x;
        m[3][r][c] = f23.y;
    }

    float row0[8], row1[8];
#pragma unroll
    for (int q = 0; q < 4; ++q) {
        float r0[4], r1[4];
#pragma unroll
        for (int c = 0; c < 4; ++c) {
            r0[c] = m[q][0][c] + m[q][1][c] + m[q][2][c];
            r1[c] = m[q][1][c] - m[q][2][c] - m[q][3][c];
        }
        row0[2 * q]     = r0[0] + r0[1] + r0[2];
        row0[2 * q + 1] = r0[1] - r0[2] - r0[3];
        row1[2 * q]     = r1[0] + r1[1] + r1[2];
        row1[2 * q + 1] = r1[1] - r1[2] - r1[3];
    }

    float* pp = out + ((size_t)co * H + 2 * ty) * W + 8 * qx;
    *(float4*)pp       = make_float4(row0[0], row0[1], row0[2], row0[3]);
    *(float4*)(pp + 4) = make_float4(row0[4], row0[5], row0[6], row0[7]);
    *(float4*)(pp + W)     = make_float4(row1[0], row1[1], row1[2], row1[3]);
    *(float4*)(pp + W + 4) = make_float4(row1[4], row1[5], row1[6], row1[7]);
}

extern "C" void kernel_launch(void* const* d_in, const int* in_sizes, int n_in,
                              void* d_out, int out_size) {
    const float* x = (const float*)d_in[0];   // [1,256,224,224]
    const float* w = (const float*)d_in[1];   // [256,256,3,3]
    float* out = (float*)d_out;               // [256,224,224]
    (void)in_sizes; (void)n_in; (void)out_size;

    wino_w_kernel<<<(C * C + 255) / 256, 256>>>(w);
    wino_in_kernel<<<dim3(49, C), 128>>>(x);

    static int smem_set = 0;
    if (!smem_set) {
        cudaFuncSetAttribute(wino_gemm_kernel,
                             cudaFuncAttributeMaxDynamicSharedMemorySize, SMEM_SZ);
        smem_set = 1;
    }
    wino_gemm_kernel<<<NCTA, 256, SMEM_SZ>>>();
    wino_out_kernel<<<dim3(25, C), 128>>>(out);
}